// round 11
// baseline (speedup 1.0000x reference)
#include <cuda_runtime.h>
#include <cuda_bf16.h>
#include <cstdint>

#define BB 16
#define TT 64
#define CC 512

// ---------------------------------------------------------------------------
// Device scratch (allocation-free rule)
// ---------------------------------------------------------------------------
__device__ float g_VE[BB * TT * CC];              // x @ W_proj + b_proj (fp32)
__device__ __nv_bfloat16 g_XEh[BB * TT * CC];     // x @ W_x + b_x (bf16)
__device__ __nv_bfloat16 g_WT[3 * CC * CC];       // [Wim^T | Wp^T | Wx^T] bf16 [N][K]

// ---------------------------------------------------------------------------
// Helpers (baseline sm_80+ PTX: mma.sync / ldmatrix / cp.async / tanh.approx)
// ---------------------------------------------------------------------------
__device__ __forceinline__ uint32_t smem_u32(const void* p) {
    uint32_t a;
    asm("{ .reg .u64 t; cvta.to.shared.u64 t, %1; cvt.u32.u64 %0, t; }" : "=r"(a) : "l"(p));
    return a;
}
__device__ __forceinline__ void ldsm4(uint32_t* r, uint32_t addr) {
    asm volatile("ldmatrix.sync.aligned.m8n8.x4.shared.b16 {%0,%1,%2,%3}, [%4];"
        : "=r"(r[0]), "=r"(r[1]), "=r"(r[2]), "=r"(r[3]) : "r"(addr));
}
__device__ __forceinline__ void mma_bf16(float* d, const uint32_t* a, const uint32_t* b) {
    asm volatile("mma.sync.aligned.m16n8k16.row.col.f32.bf16.bf16.f32 "
        "{%0,%1,%2,%3}, {%4,%5,%6,%7}, {%8,%9}, {%0,%1,%2,%3};"
        : "+f"(d[0]), "+f"(d[1]), "+f"(d[2]), "+f"(d[3])
        : "r"(a[0]), "r"(a[1]), "r"(a[2]), "r"(a[3]), "r"(b[0]), "r"(b[1]));
}
__device__ __forceinline__ void cp_async16(uint32_t dst, const void* src) {
    asm volatile("cp.async.cg.shared.global [%0], [%1], 16;" :: "r"(dst), "l"(src));
}
__device__ __forceinline__ float tanh_fast(float v) {
    float y;
    asm("tanh.approx.f32 %0, %1;" : "=f"(y) : "f"(v));
    return y;
}
#define CP_COMMIT()  asm volatile("cp.async.commit_group;" ::: "memory")
#define CP_WAIT0()   asm volatile("cp.async.wait_group 0;" ::: "memory")

// temporal smem byte offsets (total 108544 -> 2 CTAs/SM)
#define OFF_F0     0           /* [64]  */
#define OFF_F1     256
#define OFF_MASK   512
#define OFF_SOUT2  768
#define OFF_SEXP   1024        /* [128] */
#define OFF_BIM    1536        /* [512] */
#define OFF_WT0    3584
#define OFF_WT1    5632
#define OFF_BT     7680
#define OFF_A      10240       /* A: [64][512] bf16 swizzled = 65536 B */
#define OFF_B      75776       /* B: 2 x 16384 double buffer           */
#define SMEM_BYTES 108544

// embed_mma smem: A [64][512] bf16 = 64 KB, B 2 x 16 KB
#define EMB_OFF_B   65536
#define EMB_SMEM    98304

// ---------------------------------------------------------------------------
// Kernel: transpose + cvt all three weight matrices to bf16 [N][K]
// ---------------------------------------------------------------------------
__global__ void prep_w_kernel(const float* __restrict__ Wim,
                              const float* __restrict__ Wp,
                              const float* __restrict__ Wx)
{
    __shared__ float tile[32][33];
    const int z = blockIdx.z;
    const float* src = (z == 0) ? Wim : (z == 1) ? Wp : Wx;
    const int n0 = blockIdx.x * 32, k0 = blockIdx.y * 32;
    tile[threadIdx.y][threadIdx.x] = src[(k0 + threadIdx.y) * CC + n0 + threadIdx.x];
    __syncthreads();
    g_WT[(size_t)(z * CC + n0 + threadIdx.y) * CC + k0 + threadIdx.x] =
        __float2bfloat16(tile[threadIdx.x][threadIdx.y]);
}

// ---------------------------------------------------------------------------
// Kernel: embedding GEMMs on tensor cores.
// [1024, 1024] = x[1024, 512] @ [Wp | Wx][512, 1024]  (bf16, fp32 accum)
// VE half written fp32, XE half written bf16.
// ---------------------------------------------------------------------------
__global__ __launch_bounds__(256, 2) void embed_mma_kernel(
    const float* __restrict__ x,
    const float* __restrict__ bp, const float* __restrict__ bx)
{
    extern __shared__ char sm[];
    const uint32_t smb = smem_u32(sm);
    const int tid = threadIdx.x, lane = tid & 31, wid = tid >> 5;
    const int mt = blockIdx.x & 15, nt = blockIdx.x >> 4;
    const int r0 = mt * 64;

    auto issueB = [&](int s) {
        const int n  = tid >> 1;
        const int cq = (tid & 1) * 4;
        const uint32_t dstRow = smb + EMB_OFF_B + (s & 1) * 16384 + n * 128;
        const __nv_bfloat16* src = g_WT + (size_t)(CC + nt * 128 + n) * CC + s * 64 + cq * 8;
#pragma unroll
        for (int c = 0; c < 4; c++)
            cp_async16(dstRow + (((cq + c) ^ (n & 7)) << 4), src + c * 8);
        CP_COMMIT();
    };
    issueB(0);

    // A = x rows [r0, r0+64) cvt to bf16, swizzled
    {
        const int rbase = wid * 8;
#pragma unroll
        for (int rr = 0; rr < 8; rr++) {
            const int r = rbase + rr;
            const float* xr = x + (size_t)(r0 + r) * CC;
            char* Arow = sm + r * 1024;
            const int xw = r & 7;
#pragma unroll
            for (int pass = 0; pass < 4; pass++) {
                const int k = pass * 128 + lane * 4;
                const float4 xv = *(const float4*)(xr + k);
                uint2 pk;
                ((__nv_bfloat162*)&pk)[0] = __floats2bfloat162_rn(xv.x, xv.y);
                ((__nv_bfloat162*)&pk)[1] = __floats2bfloat162_rn(xv.z, xv.w);
                const int c8 = pass * 16 + (lane >> 1);
                *(uint2*)(Arow + ((c8 ^ xw) << 4) + ((lane & 1) << 3)) = pk;
            }
        }
    }

    const int mw = wid & 1, nw = wid >> 1;
    const int mA  = mw * 32 + (lane & 15);
    const int aC8 = lane >> 4;
    const int aXr = mA & 7;
    const uint32_t aBase = smb + mA * 1024;
    const int nB  = nw * 32 + (lane & 7) + ((lane >> 4) << 3);
    const int bC8 = (lane >> 3) & 1;
    const int bXr = nB & 7;
    const uint32_t bRowOff = (uint32_t)nB * 128;

    float acc[2][4][4];
#pragma unroll
    for (int mf = 0; mf < 2; mf++)
#pragma unroll
        for (int nf = 0; nf < 4; nf++)
#pragma unroll
            for (int d = 0; d < 4; d++) acc[mf][nf][d] = 0.f;

#pragma unroll 1
    for (int s = 0; s < 8; s++) {
        CP_WAIT0();
        __syncthreads();
        if (s < 7) issueB(s + 1);
        const uint32_t Bslot = smb + EMB_OFF_B + (s & 1) * 16384;
#pragma unroll
        for (int t = 0; t < 4; t++) {
            uint32_t a0[4], a1[4], b0[4], b1[4];
            const uint32_t swA = (uint32_t)(((s * 8 + t * 2 + aC8) ^ aXr) << 4);
            ldsm4(a0, aBase + swA);
            ldsm4(a1, aBase + 16384 + swA);
            const uint32_t swB = (uint32_t)(((t * 2 + bC8) ^ bXr) << 4);
            const uint32_t bA = Bslot + bRowOff + swB;
            ldsm4(b0, bA);
            ldsm4(b1, bA + 2048);
            mma_bf16(acc[0][0], a0, b0);
            mma_bf16(acc[0][1], a0, b0 + 2);
            mma_bf16(acc[0][2], a0, b1);
            mma_bf16(acc[0][3], a0, b1 + 2);
            mma_bf16(acc[1][0], a1, b0);
            mma_bf16(acc[1][1], a1, b0 + 2);
            mma_bf16(acc[1][2], a1, b1);
            mma_bf16(acc[1][3], a1, b1 + 2);
        }
    }

    // epilogue: +bias; VE -> fp32, XE -> bf16
    const int qrow = lane >> 2, qcol2 = (lane & 3) * 2;
    const int cbase = (nt & 3) * 128 + nw * 32;
    const float* bias = (nt < 4) ? bp : bx;
    float2 bb[4];
#pragma unroll
    for (int nf = 0; nf < 4; nf++)
        bb[nf] = *(const float2*)(bias + cbase + nf * 8 + qcol2);

    if (nt < 4) {
#pragma unroll
        for (int mf = 0; mf < 2; mf++)
#pragma unroll
            for (int h = 0; h < 2; h++) {
                const int row = r0 + mw * 32 + mf * 16 + h * 8 + qrow;
#pragma unroll
                for (int nf = 0; nf < 4; nf++) {
                    const int col = cbase + nf * 8 + qcol2;
                    *(float2*)(g_VE + (size_t)row * CC + col) =
                        make_float2(acc[mf][nf][h * 2] + bb[nf].x,
                                    acc[mf][nf][h * 2 + 1] + bb[nf].y);
                }
            }
    } else {
#pragma unroll
        for (int mf = 0; mf < 2; mf++)
#pragma unroll
            for (int h = 0; h < 2; h++) {
                const int row = r0 + mw * 32 + mf * 16 + h * 8 + qrow;
#pragma unroll
                for (int nf = 0; nf < 4; nf++) {
                    const int col = cbase + nf * 8 + qcol2;
                    *(__nv_bfloat162*)(g_XEh + (size_t)row * CC + col) =
                        __floats2bfloat162_rn(acc[mf][nf][h * 2] + bb[nf].x,
                                              acc[mf][nf][h * 2 + 1] + bb[nf].y);
                }
            }
    }
}

// ---------------------------------------------------------------------------
// Main fused kernel: one CTA per (b, i). M=64 j-rows, K=512, N=512 in
// 4 chunks of 128. 256 threads = 8 warps (2 mw x 4 nw), warp tile 32m x 32n.
// 2 CTAs/SM co-residency hides the serialized phases.
// ---------------------------------------------------------------------------
__global__ __launch_bounds__(256, 2) void temporal_kernel(
    const float* __restrict__ x,
    const float* __restrict__ ts,
    const float* __restrict__ amask,
    const float* __restrict__ Wt,  const float* __restrict__ bt,
    const float* __restrict__ bim,
    float* __restrict__ out)
{
    extern __shared__ char sm[];
    const uint32_t smb = smem_u32(sm);
    const int tid  = threadIdx.x;
    const int lane = tid & 31;
    const int wid  = tid >> 5;

    const int b = blockIdx.x >> 6;
    const int i = blockIdx.x & 63;

    // B stage loader: stage = [128 n][64 k] bf16 = 16 KB, XOR-swizzled
    auto issueB = [&](int ch, int s) {
        const int n  = tid >> 1;
        const int cq = (tid & 1) * 4;
        const uint32_t dstRow = smb + OFF_B + (s & 1) * 16384 + n * 128;
        const __nv_bfloat16* src = g_WT + (size_t)(ch * 128 + n) * CC + s * 64 + cq * 8;
#pragma unroll
        for (int c = 0; c < 4; c++)
            cp_async16(dstRow + (((cq + c) ^ (n & 7)) << 4), src + c * 8);
        CP_COMMIT();
    };
    issueB(0, 0);   // in flight during staging + A-build

    float* f0s   = (float*)(sm + OFF_F0);     // [64]
    float* f1s   = (float*)(sm + OFF_F1);
    float* maskv = (float*)(sm + OFF_MASK);
    float* sout2 = (float*)(sm + OFF_SOUT2);  // [64]
    float* sexp  = (float*)(sm + OFF_SEXP);   // [128]
    float* sbim  = (float*)(sm + OFF_BIM);
    float* sWt0  = (float*)(sm + OFF_WT0);
    float* sWt1  = (float*)(sm + OFF_WT1);
    float* sbt   = (float*)(sm + OFF_BT);

    // ---- staging ----
    sbim[tid] = bim[tid];       sbim[tid + 256] = bim[tid + 256];
    sWt0[tid] = Wt[tid];        sWt0[tid + 256] = Wt[tid + 256];
    sWt1[tid] = Wt[CC + tid];   sWt1[tid + 256] = Wt[CC + tid + 256];
    sbt[tid]  = bt[tid];        sbt[tid + 256]  = bt[tid + 256];
    if (tid < 64) {
        const float rel = ts[b * TT + i] - ts[b * TT + tid];
        f0s[tid] = log1pf(fmaxf(rel, 0.f));
        f1s[tid] = log1pf(fmaxf(-rel, 0.f));
        maskv[tid] = amask[b * TT + tid];
        sout2[tid] = 0.f;
    }
    if (tid < 128) sexp[tid] = 0.f;
    __syncthreads();

    // ---- build A = relu(h) [64 j][512 k] bf16, XOR-swizzled 16B chunks ----
    // warp w owns rows [w*8, w*8+8); lanes sweep 8 k each (coalesced bf16).
    {
        const int rbase = wid * 8;
#pragma unroll
        for (int rr = 0; rr < 8; rr++) {
            const int r = rbase + rr;
            const float f0v = f0s[r], f1v = f1s[r];
            const __nv_bfloat16* XEr = g_XEh + (size_t)(b * TT + r) * CC;
            char* Arow = sm + OFF_A + r * 1024;
            const int xr = r & 7;
#pragma unroll
            for (int pass = 0; pass < 2; pass++) {
                const int k = pass * 256 + lane * 8;
                const uint4 xp = *(const uint4*)(XEr + k);
                const __nv_bfloat162* x2 = (const __nv_bfloat162*)&xp;
                uint4 pk;
                __nv_bfloat162* p2 = (__nv_bfloat162*)&pk;
#pragma unroll
                for (int q = 0; q < 4; q++) {
                    const float2 xe = __bfloat1622float2(x2[q]);
                    const int kk = k + q * 2;
                    const float h0 = fmaxf(fmaf(f0v, sWt0[kk],     fmaf(f1v, sWt1[kk],     sbt[kk]))     + xe.x, 0.f);
                    const float h1 = fmaxf(fmaf(f0v, sWt0[kk + 1], fmaf(f1v, sWt1[kk + 1], sbt[kk + 1])) + xe.y, 0.f);
                    p2[q] = __floats2bfloat162_rn(h0, h1);
                }
                const int c8 = pass * 32 + lane;
                *(uint4*)(Arow + ((c8 ^ xr) << 4)) = pk;
            }
        }
    }

    // ---- warp/lane geometry ----
    const int mw = wid & 1, nw = wid >> 1;
    const int m0  = mw * 32;
    const int n0w = nw * 32;
    const int mA  = m0 + (lane & 15);
    const int aC8 = lane >> 4;
    const int aXr = mA & 7;
    const uint32_t aBase = smb + OFF_A + mA * 1024;
    const int nB  = n0w + (lane & 7) + ((lane >> 4) << 3);
    const int bC8 = (lane >> 3) & 1;
    const int bXr = nB & 7;
    const uint32_t bRowOff = (uint32_t)nB * 128;
    const int qrow = lane >> 2, qcol2 = (lane & 3) * 2;

#pragma unroll 1
    for (int ch = 0; ch < 4; ch++) {
        float acc[2][4][4];
#pragma unroll
        for (int mf = 0; mf < 2; mf++)
#pragma unroll
            for (int nf = 0; nf < 4; nf++)
#pragma unroll
                for (int d = 0; d < 4; d++) acc[mf][nf][d] = 0.f;

#pragma unroll 1
        for (int s = 0; s < 8; s++) {
            CP_WAIT0();          // stage s data complete
            __syncthreads();     // all warps past MMAs reading the other slot
            if (s < 7)            issueB(ch, s + 1);
            else if (ch < 3)      issueB(ch + 1, 0);    // overlaps epilogue
            const uint32_t Bslot = smb + OFF_B + (s & 1) * 16384;
#pragma unroll
            for (int t = 0; t < 4; t++) {
                uint32_t a0[4], a1[4], b0[4], b1[4];
                const uint32_t swA = (uint32_t)(((s * 8 + t * 2 + aC8) ^ aXr) << 4);
                ldsm4(a0, aBase + swA);
                ldsm4(a1, aBase + 16384 + swA);
                const uint32_t swB = (uint32_t)(((t * 2 + bC8) ^ bXr) << 4);
                const uint32_t bA = Bslot + bRowOff + swB;
                ldsm4(b0, bA);
                ldsm4(b1, bA + 2048);
                mma_bf16(acc[0][0], a0, b0);
                mma_bf16(acc[0][1], a0, b0 + 2);
                mma_bf16(acc[0][2], a0, b1);
                mma_bf16(acc[0][3], a0, b1 + 2);
                mma_bf16(acc[1][0], a1, b0);
                mma_bf16(acc[1][1], a1, b0 + 2);
                mma_bf16(acc[1][2], a1, b1);
                mma_bf16(acc[1][3], a1, b1 + 2);
            }
        }

        // ---- register epilogue: sigmoid via tanh.approx, fused reductions ----
        float bimv[8], cs[8];
#pragma unroll
        for (int nf = 0; nf < 4; nf++) {
            bimv[nf * 2]     = sbim[ch * 128 + n0w + nf * 8 + qcol2];
            bimv[nf * 2 + 1] = sbim[ch * 128 + n0w + nf * 8 + qcol2 + 1];
            cs[nf * 2] = 0.f; cs[nf * 2 + 1] = 0.f;
        }
        float rs[4];
#pragma unroll
        for (int mf = 0; mf < 2; mf++) {
#pragma unroll
            for (int h = 0; h < 2; h++) {
                const int r  = m0 + mf * 16 + h * 8 + qrow;
                const float hmk = 0.5f * maskv[r];
                const float* VEr = g_VE + (size_t)(b * TT + r) * CC
                                   + ch * 128 + n0w + qcol2;
                float rsum = 0.f;
#pragma unroll
                for (int nf = 0; nf < 4; nf++) {
                    const float2 ve = *(const float2*)(VEr + nf * 8);
                    const float s0 = acc[mf][nf][h * 2 + 0] + bimv[nf * 2];
                    const float s1 = acc[mf][nf][h * 2 + 1] + bimv[nf * 2 + 1];
                    const float p0 = fmaf(tanh_fast(0.5f * s0), hmk, hmk);
                    const float p1 = fmaf(tanh_fast(0.5f * s1), hmk, hmk);
                    rsum += p0 + p1;
                    cs[nf * 2]     += __expf(ve.x * p0);
                    cs[nf * 2 + 1] += __expf(ve.y * p1);
                }
                rs[mf * 2 + h] = rsum;
            }
        }
        // row sums -> sout2 (reduce over the 4 qcol lanes)
#pragma unroll
        for (int q = 0; q < 4; q++) {
            rs[q] += __shfl_xor_sync(0xffffffffu, rs[q], 1);
            rs[q] += __shfl_xor_sync(0xffffffffu, rs[q], 2);
        }
        if ((lane & 3) == 0) {
#pragma unroll
            for (int q = 0; q < 4; q++)
                atomicAdd(&sout2[m0 + (q >> 1) * 16 + (q & 1) * 8 + qrow], rs[q]);
        }
        // column exp-sums -> sexp (reduce over the 8 qrow lanes)
#pragma unroll
        for (int c = 0; c < 8; c++) {
            cs[c] += __shfl_xor_sync(0xffffffffu, cs[c], 4);
            cs[c] += __shfl_xor_sync(0xffffffffu, cs[c], 8);
            cs[c] += __shfl_xor_sync(0xffffffffu, cs[c], 16);
        }
        if (lane < 4) {
#pragma unroll
            for (int nf = 0; nf < 4; nf++) {
                atomicAdd(&sexp[n0w + nf * 8 + lane * 2],     cs[nf * 2]);
                atomicAdd(&sexp[n0w + nf * 8 + lane * 2 + 1], cs[nf * 2 + 1]);
            }
        }
        __syncthreads();

        // out1 = x + log(sum_j exp(z)) for this chunk's 128 columns
        if (tid < 128) {
            const int ng = ch * 128 + tid;
            const int row = b * TT + i;
            out[(size_t)row * CC + ng] = x[(size_t)row * CC + ng] + __logf(sexp[tid]);
            sexp[tid] = 0.f;
        }
        __syncthreads();
    }

    // ---- out2: mean over C ----
    if (tid < 64) {
        out[BB * TT * CC + ((b * TT + i) * TT + tid)] = sout2[tid] * (1.f / 512.f);
    }
}

// ---------------------------------------------------------------------------
extern "C" void kernel_launch(void* const* d_in, const int* in_sizes, int n_in,
                              void* d_out, int out_size)
{
    const float* x     = (const float*)d_in[0];
    const float* ts    = (const float*)d_in[1];
    const float* amask = (const float*)d_in[2];
    const float* Wp    = (const float*)d_in[3];
    const float* bp    = (const float*)d_in[4];
    const float* Wx    = (const float*)d_in[5];
    const float* bx    = (const float*)d_in[6];
    const float* Wt    = (const float*)d_in[7];
    const float* bt    = (const float*)d_in[8];
    const float* Wim   = (const float*)d_in[9];
    const float* bim   = (const float*)d_in[10];
    float* out = (float*)d_out;

    prep_w_kernel<<<dim3(16, 16, 3), dim3(32, 32)>>>(Wim, Wp, Wx);

    cudaFuncSetAttribute(embed_mma_kernel, cudaFuncAttributeMaxDynamicSharedMemorySize, EMB_SMEM);
    embed_mma_kernel<<<128, 256, EMB_SMEM>>>(x, bp, bx);

    cudaFuncSetAttribute(temporal_kernel, cudaFuncAttributeMaxDynamicSharedMemorySize, SMEM_BYTES);
    temporal_kernel<<<BB * TT, 256, SMEM_BYTES>>>(x, ts, amask, Wt, bt, bim, out);
}